// round 15
// baseline (speedup 1.0000x reference)
#include <cuda_runtime.h>
#include <cuda_fp16.h>
#include <math.h>
#include <stdint.h>

#define Nn  50000
#define Ein 800000
#define ET  850000      // Ein + Nn self loops
#define FIN 256
#define HID 64
#define H1  4
#define NT  512         // xl (256) ++ xr (256)
#define NMB 391         // ceil(Nn/128)

// ---------------- scratch (device globals; no allocation allowed) ----------
__device__ __align__(16) __half g_x1h[(size_t)Nn * NT];   // layer1 proj fp16 [xl|xr]
__device__ __align__(16) __half g_x2h[(size_t)Nn * 128];  // layer2 proj fp16 [xl2|xr2]
__device__ __align__(16) __half g_xh [Nn * FIN];          // x rounded to fp16
__device__ __align__(16) __half g_whi[NT * FIN];          // W1t[n][k] fp16 hi
__device__ __align__(16) __half g_wlo[NT * FIN];          // W1t[n][k] fp16 lo
__device__ __align__(16) __half g_hh [Nn * HID];          // layer1 output h, fp16
__device__ __align__(16) __half g_w2hi[128 * 64];         // W2t[n][k] fp16 hi
__device__ __align__(16) __half g_w2lo[128 * 64];         // W2t[n][k] fp16 lo

__device__ int g_deg[Nn];
__device__ int g_cur[Nn];
__device__ int g_off[Nn + 1];
__device__ int g_csrc[ET];

__device__ __forceinline__ float lrelu(float z) {
    return fmaxf(z, 0.f) + 0.2f * fminf(z, 0.f);
}

__device__ __forceinline__ void h8tof(uint4 v, float* f) {
    const __half2* h = (const __half2*)&v;
#pragma unroll
    for (int j = 0; j < 4; j++) {
        float2 t = __half22float2(h[j]);
        f[2 * j] = t.x; f[2 * j + 1] = t.y;
    }
}

// ---------------- CSR build ----------------
__global__ void k_zero() {
    int i = blockIdx.x * blockDim.x + threadIdx.x;
    if (i < Nn) { g_deg[i] = 0; g_cur[i] = 0; }
}

__global__ void k_hist(const int* __restrict__ dst) {
    int e = blockIdx.x * blockDim.x + threadIdx.x;
    if (e >= ET) return;
    int d = (e < Ein) ? dst[e] : (e - Ein);
    atomicAdd(&g_deg[d], 1);
}

__global__ void k_scan() {   // single block, 1024 threads, 4 elems/thread
    __shared__ int wsum[32];
    __shared__ int carry_s;
    int t = threadIdx.x;
    if (t == 0) carry_s = 0;
    __syncthreads();
    for (int base = 0; base < Nn; base += 4096) {
        int i0 = base + t * 4;
        int v0 = (i0 + 0 < Nn) ? g_deg[i0 + 0] : 0;
        int v1 = (i0 + 1 < Nn) ? g_deg[i0 + 1] : 0;
        int v2 = (i0 + 2 < Nn) ? g_deg[i0 + 2] : 0;
        int v3 = (i0 + 3 < Nn) ? g_deg[i0 + 3] : 0;
        int tsum = v0 + v1 + v2 + v3;
        int x = tsum;
#pragma unroll
        for (int o = 1; o < 32; o <<= 1) {
            int y = __shfl_up_sync(0xffffffffu, x, o);
            if ((t & 31) >= o) x += y;
        }
        if ((t & 31) == 31) wsum[t >> 5] = x;
        __syncthreads();
        if (t < 32) {
            int wv = wsum[t];
#pragma unroll
            for (int o = 1; o < 32; o <<= 1) {
                int y = __shfl_up_sync(0xffffffffu, wv, o);
                if (t >= o) wv += y;
            }
            wsum[t] = wv;
        }
        __syncthreads();
        int excl = x - tsum + ((t >> 5) ? wsum[(t >> 5) - 1] : 0) + carry_s;
        if (i0 + 0 < Nn) g_off[i0 + 0] = excl;
        if (i0 + 1 < Nn) g_off[i0 + 1] = excl + v0;
        if (i0 + 2 < Nn) g_off[i0 + 2] = excl + v0 + v1;
        if (i0 + 3 < Nn) g_off[i0 + 3] = excl + v0 + v1 + v2;
        int tot = wsum[31];
        __syncthreads();
        if (t == 0) carry_s += tot;
        __syncthreads();
    }
    if (t == 0) g_off[Nn] = carry_s;
}

__global__ void k_fill(const int* __restrict__ src, const int* __restrict__ dst) {
    int e = blockIdx.x * blockDim.x + threadIdx.x;
    if (e >= ET) return;
    int s, d;
    if (e < Ein) { s = src[e]; d = dst[e]; }
    else         { s = e - Ein; d = s; }
    int p = atomicAdd(&g_cur[d], 1);
    g_csrc[g_off[d] + p] = s;
}

// ---------------- conversions ----------------
__global__ void k_convx(const float* __restrict__ x) {
    int i = blockIdx.x * blockDim.x + threadIdx.x;
    if (i >= Nn * FIN) return;
    g_xh[i] = __float2half(x[i]);
}

__global__ void k_convw(const float* __restrict__ Wl, const float* __restrict__ Wr) {
    int i = blockIdx.x * blockDim.x + threadIdx.x;
    if (i >= NT * FIN) return;
    int n = i >> 8, k = i & 255;   // FIN = 256
    float v = (n < 256) ? Wl[k * 256 + n] : Wr[k * 256 + (n - 256)];
    __half hi = __float2half(v);
    g_whi[i] = hi;
    g_wlo[i] = __float2half(v - __half2float(hi));
}

__global__ void k_convw2(const float* __restrict__ Wl, const float* __restrict__ Wr) {
    int i = blockIdx.x * blockDim.x + threadIdx.x;
    if (i >= 128 * 64) return;
    int n = i >> 6, k = i & 63;
    float v = (n < 64) ? Wl[k * 64 + n] : Wr[k * 64 + (n - 64)];
    __half hi = __float2half(v);
    g_w2hi[i] = hi;
    g_w2lo[i] = __float2half(v - __half2float(hi));
}

// ---------------- mma helper ----------------
__device__ __forceinline__ void mma16816h(float* c, const uint32_t* a, uint32_t b0, uint32_t b1) {
    asm volatile(
        "mma.sync.aligned.m16n8k16.row.col.f32.f16.f16.f32 "
        "{%0,%1,%2,%3}, {%4,%5,%6,%7}, {%8,%9}, {%0,%1,%2,%3};"
        : "+f"(c[0]), "+f"(c[1]), "+f"(c[2]), "+f"(c[3])
        : "r"(a[0]), "r"(a[1]), "r"(a[2]), "r"(a[3]), "r"(b0), "r"(b1));
}

// ---------------- layer1 GEMM: persistent, B-resident ----------------
// grid (4, 37): CTA owns n-block (128 cols of 512) + loops m-blocks (step 37).
// smem: B hi/lo full-K resident (stride 264), A tile full-K per m-block.
#define TS2 264
#define S2_BH 0
#define S2_BL (128 * TS2)
#define S2_A  (2 * 128 * TS2)
#define S2_ELEMS (3 * 128 * TS2)       // 101376 halfs = 202752 B

__global__ void __launch_bounds__(256, 1) k_gemm1() {
    extern __shared__ __half sm[];
    int tid = threadIdx.x;
    int wid = tid >> 5, lane = tid & 31;
    int n0 = blockIdx.x * 128;
    int wm = (wid & 1) * 64, wn = (wid >> 1) * 32;
    int gr = lane >> 2, gc2 = (lane & 3) * 2;

    // load B hi+lo once (128 rows x 256 K)
    for (int u = tid; u < 4096; u += 256) {
        int r = u >> 5, i = u & 31;
        uint4 vh = ((const uint4*)(g_whi + (size_t)(n0 + r) * FIN))[i];
        uint4 vl = ((const uint4*)(g_wlo + (size_t)(n0 + r) * FIN))[i];
        *(uint4*)(sm + S2_BH + r * TS2 + i * 8) = vh;
        *(uint4*)(sm + S2_BL + r * TS2 + i * 8) = vl;
    }
    __syncthreads();

    for (int mb = blockIdx.y; mb < NMB; mb += 37) {
        int m0 = mb * 128;

        // load A tile (128 rows x 256 K fp16)
        for (int u = tid; u < 4096; u += 256) {
            int r = u >> 5, i = u & 31;
            int m = m0 + r;
            uint4 v = make_uint4(0u, 0u, 0u, 0u);
            if (m < Nn) v = ((const uint4*)(g_xh + (size_t)m * FIN))[i];
            *(uint4*)(sm + S2_A + r * TS2 + i * 8) = v;
        }
        __syncthreads();

        float acc[4][4][4];
#pragma unroll
        for (int mi = 0; mi < 4; mi++)
#pragma unroll
            for (int f = 0; f < 4; f++)
#pragma unroll
                for (int j = 0; j < 4; j++) acc[mi][f][j] = 0.f;

#pragma unroll
        for (int kk = 0; kk < 256; kk += 16) {
            uint32_t a[4][4];
#pragma unroll
            for (int mi = 0; mi < 4; mi++) {
                int r0 = wm + mi * 16 + gr;
                a[mi][0] = *(const uint32_t*)(sm + S2_A + (r0)     * TS2 + kk + gc2);
                a[mi][1] = *(const uint32_t*)(sm + S2_A + (r0 + 8) * TS2 + kk + gc2);
                a[mi][2] = *(const uint32_t*)(sm + S2_A + (r0)     * TS2 + kk + gc2 + 8);
                a[mi][3] = *(const uint32_t*)(sm + S2_A + (r0 + 8) * TS2 + kk + gc2 + 8);
            }
#pragma unroll
            for (int f = 0; f < 4; f++) {
                int nb = wn + f * 8 + gr;
                uint32_t bh0 = *(const uint32_t*)(sm + S2_BH + nb * TS2 + kk + gc2);
                uint32_t bh1 = *(const uint32_t*)(sm + S2_BH + nb * TS2 + kk + gc2 + 8);
                uint32_t bl0 = *(const uint32_t*)(sm + S2_BL + nb * TS2 + kk + gc2);
                uint32_t bl1 = *(const uint32_t*)(sm + S2_BL + nb * TS2 + kk + gc2 + 8);
#pragma unroll
                for (int mi = 0; mi < 4; mi++) {
                    mma16816h(acc[mi][f], a[mi], bh0, bh1);
                    mma16816h(acc[mi][f], a[mi], bl0, bl1);
                }
            }
        }

        // epilogue -> g_x1h fp16
#pragma unroll
        for (int mi = 0; mi < 4; mi++) {
            int r0 = m0 + wm + mi * 16 + gr;
#pragma unroll
            for (int f = 0; f < 4; f++) {
                int col = n0 + wn + f * 8 + gc2;
                if (r0 < Nn)
                    *(__half2*)(g_x1h + (size_t)r0 * NT + col) =
                        __floats2half2_rn(acc[mi][f][0], acc[mi][f][1]);
                if (r0 + 8 < Nn)
                    *(__half2*)(g_x1h + (size_t)(r0 + 8) * NT + col) =
                        __floats2half2_rn(acc[mi][f][2], acc[mi][f][3]);
            }
        }
        __syncthreads();   // protect A before next m-block overwrites
    }
}

// ---------------- layer2 GEMM via mma.sync fp16 2-term (K=64, N=128) ------
#define TS 72
#define SM_A  0
#define SM_BH (128 * TS)
#define SM_BL (2 * 128 * TS)
#define SM_ELEMS (3 * 128 * TS)

__global__ void __launch_bounds__(256, 2) k_gemm2() {
    extern __shared__ __half sm[];
    int tid = threadIdx.x;
    int wid = tid >> 5, lane = tid & 31;
    int m0 = blockIdx.x * 128;
    int wm = (wid & 3) * 32, wn = (wid >> 2) * 64;
    int gr = lane >> 2, gc2 = (lane & 3) * 2;

    float acc[2][8][4];
#pragma unroll
    for (int mi = 0; mi < 2; mi++)
#pragma unroll
        for (int f = 0; f < 8; f++)
#pragma unroll
            for (int j = 0; j < 4; j++) acc[mi][f][j] = 0.f;

#pragma unroll
    for (int u = tid; u < 1024; u += 256) {
        int r = u >> 3, i = u & 7;
        int m = m0 + r;
        uint4 v = make_uint4(0u, 0u, 0u, 0u);
        if (m < Nn) v = ((const uint4*)(g_hh + (size_t)m * HID))[i];
        *(uint4*)(sm + SM_A + r * TS + i * 8) = v;
    }
#pragma unroll
    for (int u = tid; u < 1024; u += 256) {
        int r = u >> 3, i = u & 7;
        uint4 vh = ((const uint4*)(g_w2hi + r * 64))[i];
        uint4 vl = ((const uint4*)(g_w2lo + r * 64))[i];
        *(uint4*)(sm + SM_BH + r * TS + i * 8) = vh;
        *(uint4*)(sm + SM_BL + r * TS + i * 8) = vl;
    }
    __syncthreads();

#pragma unroll
    for (int kk = 0; kk < 64; kk += 16) {
        uint32_t a[2][4];
#pragma unroll
        for (int mi = 0; mi < 2; mi++) {
            int r0 = wm + mi * 16 + gr;
            a[mi][0] = *(const uint32_t*)(sm + SM_A + (r0)     * TS + kk + gc2);
            a[mi][1] = *(const uint32_t*)(sm + SM_A + (r0 + 8) * TS + kk + gc2);
            a[mi][2] = *(const uint32_t*)(sm + SM_A + (r0)     * TS + kk + gc2 + 8);
            a[mi][3] = *(const uint32_t*)(sm + SM_A + (r0 + 8) * TS + kk + gc2 + 8);
        }
#pragma unroll
        for (int f = 0; f < 8; f++) {
            int nb = wn + f * 8 + gr;
            uint32_t bh0 = *(const uint32_t*)(sm + SM_BH + nb * TS + kk + gc2);
            uint32_t bh1 = *(const uint32_t*)(sm + SM_BH + nb * TS + kk + gc2 + 8);
            uint32_t bl0 = *(const uint32_t*)(sm + SM_BL + nb * TS + kk + gc2);
            uint32_t bl1 = *(const uint32_t*)(sm + SM_BL + nb * TS + kk + gc2 + 8);
#pragma unroll
            for (int mi = 0; mi < 2; mi++) {
                mma16816h(acc[mi][f], a[mi], bh0, bh1);
                mma16816h(acc[mi][f], a[mi], bl0, bl1);
            }
        }
    }

#pragma unroll
    for (int mi = 0; mi < 2; mi++) {
        int r0 = m0 + wm + mi * 16 + gr;
#pragma unroll
        for (int f = 0; f < 8; f++) {
            int col = wn + f * 8 + gc2;
            if (r0 < Nn)
                *(__half2*)(g_x2h + (size_t)r0 * 128 + col) =
                    __floats2half2_rn(acc[mi][f][0], acc[mi][f][1]);
            if (r0 + 8 < Nn)
                *(__half2*)(g_x2h + (size_t)(r0 + 8) * 128 + col) =
                    __floats2half2_rn(acc[mi][f][2], acc[mi][f][3]);
        }
    }
}

// ---------------- layer1 fused attention (no-max softmax, fp16 gather) ----
__global__ void k_gat1(const float* __restrict__ att, const float* __restrict__ bias,
                       const float* __restrict__ lng, const float* __restrict__ lnb) {
    int n = (blockIdx.x * blockDim.x + threadIdx.x) >> 5;
    int lane = threadIdx.x & 31;
    if (n >= Nn) return;

    float b[8], w[8];
    h8tof(((const uint4*)(g_x1h + (size_t)n * NT + 256))[lane], b);
    {
        const float4* at = (const float4*)(att + 8 * lane);
        float4 t0 = at[0], t1 = at[1];
        w[0] = t0.x; w[1] = t0.y; w[2] = t0.z; w[3] = t0.w;
        w[4] = t1.x; w[5] = t1.y; w[6] = t1.z; w[7] = t1.w;
    }

    int beg = g_off[n], end = g_off[n + 1];
    float den = 0.f;
    float acc[8];
#pragma unroll
    for (int j = 0; j < 8; j++) acc[j] = 0.f;

    uint4 P0, P1;
    {
        int s0 = g_csrc[beg];
        P0 = ((const uint4*)(g_x1h + (size_t)s0 * NT))[lane];
        if (beg + 1 < end) {
            int s1 = g_csrc[beg + 1];
            P1 = ((const uint4*)(g_x1h + (size_t)s1 * NT))[lane];
        }
    }

    int k = beg;
    while (k + 1 < end) {
        float c[8], d[8];
        h8tof(P0, c); h8tof(P1, d);
        if (k + 2 < end) {
            int s = g_csrc[k + 2];
            P0 = ((const uint4*)(g_x1h + (size_t)s * NT))[lane];
        }
        if (k + 3 < end) {
            int s = g_csrc[k + 3];
            P1 = ((const uint4*)(g_x1h + (size_t)s * NT))[lane];
        }
        float p = 0.f, q = 0.f;
#pragma unroll
        for (int j = 0; j < 8; j++) {
            p = fmaf(lrelu(c[j] + b[j]), w[j], p);
            q = fmaf(lrelu(d[j] + b[j]), w[j], q);
        }
#pragma unroll
        for (int o = 4; o > 0; o >>= 1) {
            p += __shfl_xor_sync(0xffffffffu, p, o, 8);
            q += __shfl_xor_sync(0xffffffffu, q, o, 8);
        }
        float wp = __expf(p);
        float wq = __expf(q);
        den += wp + wq;
#pragma unroll
        for (int j = 0; j < 8; j++) acc[j] = fmaf(wp, c[j], fmaf(wq, d[j], acc[j]));
        k += 2;
    }
    if (k < end) {
        float c[8];
        h8tof(P0, c);
        float p = 0.f;
#pragma unroll
        for (int j = 0; j < 8; j++) p = fmaf(lrelu(c[j] + b[j]), w[j], p);
#pragma unroll
        for (int o = 4; o > 0; o >>= 1) p += __shfl_xor_sync(0xffffffffu, p, o, 8);
        float wp = __expf(p);
        den += wp;
#pragma unroll
        for (int j = 0; j < 8; j++) acc[j] = fmaf(wp, c[j], acc[j]);
    }

    float r = 1.f / (den + 1e-16f);
    int c0 = (lane & 7) * 8;
    float v[8];
#pragma unroll
    for (int j = 0; j < 8; j++) {
        float t = acc[j] * r;
        t += __shfl_xor_sync(0xffffffffu, t, 8);
        t += __shfl_xor_sync(0xffffffffu, t, 16);
        v[j] = 0.25f * t + bias[c0 + j];
    }

    float ssum = 0.f;
#pragma unroll
    for (int j = 0; j < 8; j++) ssum += v[j];
#pragma unroll
    for (int o = 16; o > 0; o >>= 1) ssum += __shfl_xor_sync(0xffffffffu, ssum, o);
    float mu = ssum * (1.f / 256.f);
    float sq = 0.f;
#pragma unroll
    for (int j = 0; j < 8; j++) { v[j] -= mu; sq += v[j] * v[j]; }
#pragma unroll
    for (int o = 16; o > 0; o >>= 1) sq += __shfl_xor_sync(0xffffffffu, sq, o);
    float inv = rsqrtf(sq * (1.f / 256.f) + 1e-5f);

    if (lane < 8) {
        __half hv[8];
#pragma unroll
        for (int j = 0; j < 8; j++)
            hv[j] = __float2half(fmaxf(v[j] * inv * lng[c0 + j] + lnb[c0 + j], 0.f));
        *(uint4*)(g_hh + (size_t)n * HID + c0) = *(uint4*)hv;
    }
}

// ---------------- layer2 fused attention (no-max softmax, fp16 gather) ----
__global__ void k_gat2(const float* __restrict__ att, const float* __restrict__ bias,
                       const float* __restrict__ lng, const float* __restrict__ lnb,
                       float* __restrict__ out) {
    int n = (blockIdx.x * blockDim.x + threadIdx.x) >> 5;
    int lane = threadIdx.x & 31;
    if (n >= Nn) return;

    float2 b = __half22float2(((const __half2*)(g_x2h + (size_t)n * 128 + 64))[lane]);
    float2 w = ((const float2*)att)[lane];

    int beg = g_off[n], end = g_off[n + 1];
    float den = 0.f;
    float2 acc = make_float2(0.f, 0.f);

    __half2 P0, P1;
    {
        int s0 = g_csrc[beg];
        P0 = ((const __half2*)(g_x2h + (size_t)s0 * 128))[lane];
        if (beg + 1 < end) {
            int s1 = g_csrc[beg + 1];
            P1 = ((const __half2*)(g_x2h + (size_t)s1 * 128))[lane];
        }
    }

    int k = beg;
    while (k + 1 < end) {
        float2 c = __half22float2(P0), d = __half22float2(P1);
        if (k + 2 < end) {
            int s = g_csrc[k + 2];
            P0 = ((const __half2*)(g_x2h + (size_t)s * 128))[lane];
        }
        if (k + 3 < end) {
            int s = g_csrc[k + 3];
            P1 = ((const __half2*)(g_x2h + (size_t)s * 128))[lane];
        }
        float p = lrelu(c.x + b.x) * w.x + lrelu(c.y + b.y) * w.y;
        float q = lrelu(d.x + b.x) * w.x + lrelu(d.y + b.y) * w.y;
#pragma unroll
        for (int o = 16; o > 0; o >>= 1) {
            p += __shfl_xor_sync(0xffffffffu, p, o);
            q += __shfl_xor_sync(0xffffffffu, q, o);
        }
        float wp = __expf(p);
        float wq = __expf(q);
        den += wp + wq;
        acc.x = fmaf(wp, c.x, fmaf(wq, d.x, acc.x));
        acc.y = fmaf(wp, c.y, fmaf(wq, d.y, acc.y));
        k += 2;
    }
    if (k < end) {
        float2 c = __half22float2(P0);
        float p = lrelu(c.x + b.x) * w.x + lrelu(c.y + b.y) * w.y;
#pragma unroll
        for (int o = 16; o > 0; o >>= 1) p += __shfl_xor_sync(0xffffffffu, p, o);
        float wp = __expf(p);
        den += wp;
        acc.x = fmaf(wp, c.x, acc.x);
        acc.y = fmaf(wp, c.y, acc.y);
    }

    float r = 1.f / (den + 1e-16f);
    float2 bv = ((const float2*)bias)[lane];
    float vx = acc.x * r + bv.x;
    float vy = acc.y * r + bv.y;

    float ssum = vx + vy;
#pragma unroll
    for (int o = 16; o > 0; o >>= 1) ssum += __shfl_xor_sync(0xffffffffu, ssum, o);
    float mu = ssum * (1.f / 64.f);
    float dx = vx - mu, dy = vy - mu;
    float sq = dx * dx + dy * dy;
#pragma unroll
    for (int o = 16; o > 0; o >>= 1) sq += __shfl_xor_sync(0xffffffffu, sq, o);
    float inv = rsqrtf(sq * (1.f / 64.f) + 1e-5f);

    float2 gv = ((const float2*)lng)[lane];
    float2 b2 = ((const float2*)lnb)[lane];
    float2 o;
    o.x = dx * inv * gv.x + b2.x;
    o.y = dy * inv * gv.y + b2.y;
    ((float2*)(out + (size_t)n * HID))[lane] = o;
}

// ---------------- launch ----------------
extern "C" void kernel_launch(void* const* d_in, const int* in_sizes, int n_in,
                              void* d_out, int out_size) {
    const float* x    = (const float*)d_in[0];
    const int*   ei   = (const int*)d_in[1];
    const float* W1l  = (const float*)d_in[2];
    const float* W1r  = (const float*)d_in[3];
    const float* att1 = (const float*)d_in[4];
    const float* b1   = (const float*)d_in[5];
    const float* ln1g = (const float*)d_in[6];
    const float* ln1b = (const float*)d_in[7];
    const float* W2l  = (const float*)d_in[8];
    const float* W2r  = (const float*)d_in[9];
    const float* att2 = (const float*)d_in[10];
    const float* b2   = (const float*)d_in[11];
    const float* ln2g = (const float*)d_in[12];
    const float* ln2b = (const float*)d_in[13];
    float* out = (float*)d_out;

    const int* srcp = ei;
    const int* dstp = ei + Ein;

    const int T = 256;

    // fork: CSR build on side stream, concurrent with conv + gemm1
    cudaStream_t s2;
    cudaStreamCreateWithFlags(&s2, cudaStreamNonBlocking);
    cudaEvent_t evF, evJ;
    cudaEventCreateWithFlags(&evF, cudaEventDisableTiming);
    cudaEventCreateWithFlags(&evJ, cudaEventDisableTiming);
    cudaEventRecord(evF, 0);
    cudaStreamWaitEvent(s2, evF, 0);

    k_zero<<<(Nn + T - 1) / T, T, 0, s2>>>();
    k_hist<<<(ET + T - 1) / T, T, 0, s2>>>(dstp);
    k_scan<<<1, 1024, 0, s2>>>();
    k_fill<<<(ET + T - 1) / T, T, 0, s2>>>(srcp, dstp);
    cudaEventRecord(evJ, s2);

    // main stream: conversions + layer1 GEMM
    k_convw<<<(NT * FIN + T - 1) / T, T>>>(W1l, W1r);
    k_convx<<<(Nn * FIN + T - 1) / T, T>>>(x);
    k_convw2<<<(128 * 64 + T - 1) / T, T>>>(W2l, W2r);

    cudaFuncSetAttribute(k_gemm1, cudaFuncAttributeMaxDynamicSharedMemorySize,
                         S2_ELEMS * (int)sizeof(__half));
    cudaFuncSetAttribute(k_gemm2, cudaFuncAttributeMaxDynamicSharedMemorySize,
                         SM_ELEMS * (int)sizeof(__half));
    dim3 gg(4, 37);
    k_gemm1<<<gg, 256, S2_ELEMS * sizeof(__half)>>>();

    // join CSR before the gather phase
    cudaStreamWaitEvent(0, evJ, 0);

    // layer1 fused attention + LN + relu -> g_hh (fp16)
    k_gat1<<<(Nn * 32 + T - 1) / T, T>>>(att1, b1, ln1g, ln1b);

    // layer2 GEMM: [50000,64] @ [64,128] fp16 mma 2-term
    k_gemm2<<<(Nn + 127) / 128, 256, SM_ELEMS * sizeof(__half)>>>();

    // layer2 fused attention + LN -> out
    k_gat2<<<(Nn * 32 + T - 1) / T, T>>>(att2, b2, ln2g, ln2b, out);
}